// round 6
// baseline (speedup 1.0000x reference)
#include <cuda_runtime.h>
#include <math_constants.h>

#define B_    32
#define T_    2048
#define HE_   1024
#define DECF  2048
#define S_    32
#define CHUNK (T_ / S_)          // 64 rows per CTA
#define NW    4                  // warps per CTA
#define NT    (NW * 32)          // 128 threads
#define RPW   (CHUNK / NW)       // 16 rows per warp

// Split partials + completion counters (allocation-free scratch, zero-init)
__device__ float g_m  [B_ * S_];
__device__ float g_z  [B_ * S_];
__device__ __align__(16) float g_acc[B_ * S_ * HE_];   // 4 MB
__device__ int   g_cnt[B_];

__global__ __launch_bounds__(NT, 5)
void attn_fused(const float* __restrict__ hidden,   // (2,32,1024)
                const float* __restrict__ enc,      // (32,2048,1024)
                const float* __restrict__ mask,     // (32,2048)
                const float* __restrict__ attn_w,   // (3072,)
                const float* __restrict__ attn_b,   // (1,)
                float* __restrict__ out)            // (32,1024)
{
    const int b    = blockIdx.x;
    const int s    = blockIdx.y;
    const int tid  = threadIdx.x;
    const int wid  = tid >> 5;
    const int lane = tid & 31;

    __shared__ float s_red[NW];
    __shared__ float s_hid;
    __shared__ float s_m[NW], s_z[NW];
    __shared__ __align__(16) float s_we[HE_];         // 4 KB (w_e staged)
    __shared__ __align__(16) float s_acc[NW * HE_];   // 16 KB
    __shared__ int s_last;

    // ---- stage w_e into shared ----
    #pragma unroll
    for (int k = 0; k < HE_ / NT; ++k)
        s_we[tid + k * NT] = attn_w[DECF + tid + k * NT];

    // ---- hid_dot[b] = hid_flat[b,:] @ w_h + attn_b ----
    {
        float ps = 0.f;
        #pragma unroll
        for (int k = 0; k < DECF / NT; ++k) {
            const int f = tid + k * NT;               // 0..2047
            ps += hidden[(size_t)(f >> 10) * (B_ * HE_) + (size_t)b * HE_ + (f & 1023)]
                  * attn_w[f];
        }
        #pragma unroll
        for (int o = 16; o > 0; o >>= 1) ps += __shfl_xor_sync(0xffffffffu, ps, o);
        if (lane == 0) s_red[wid] = ps;
        __syncthreads();
        if (tid == 0) {
            float h = attn_b[0];
            #pragma unroll
            for (int w = 0; w < NW; ++w) h += s_red[w];
            s_hid = h;
        }
        __syncthreads();
    }
    const float hid_dot = s_hid;

    // ---- warp-private online softmax over RPW rows (no barriers) ----
    float m = -CUDART_INF_F;
    float z = 0.f;
    float4 acc[8];
    #pragma unroll
    for (int k = 0; k < 8; ++k) acc[k] = make_float4(0.f, 0.f, 0.f, 0.f);

    const int r0 = s * CHUNK + wid * RPW;
    const float* encB = enc  + (size_t)b * T_ * HE_;
    const float* mskB = mask + (size_t)b * T_;

    for (int i = 0; i < RPW; ++i) {
        const int r = r0 + i;
        const float* row = encB + (size_t)r * HE_ + lane * 4;

        float4 v[8];
        #pragma unroll
        for (int k = 0; k < 8; ++k)
            v[k] = *reinterpret_cast<const float4*>(row + k * 128);

        float d = 0.f;
        #pragma unroll
        for (int k = 0; k < 8; ++k) {
            const float4 w4 = *reinterpret_cast<const float4*>(&s_we[lane * 4 + k * 128]);
            d += v[k].x * w4.x + v[k].y * w4.y + v[k].z * w4.z + v[k].w * w4.w;
        }
        #pragma unroll
        for (int o = 16; o > 0; o >>= 1) d += __shfl_xor_sync(0xffffffffu, d, o);

        const float mk = __ldg(mskB + r);
        const float e  = (d + hid_dot) * mk;

        const float mnew = fmaxf(m, e);
        if (mnew > m) {                     // warp-uniform branch
            const float sc = __expf(m - mnew);
            z *= sc;
            #pragma unroll
            for (int k = 0; k < 8; ++k) {
                acc[k].x *= sc; acc[k].y *= sc; acc[k].z *= sc; acc[k].w *= sc;
            }
            m = mnew;
        }
        const float wt = mk * __expf(e - m);
        z += wt;
        #pragma unroll
        for (int k = 0; k < 8; ++k) {
            acc[k].x += wt * v[k].x;
            acc[k].y += wt * v[k].y;
            acc[k].z += wt * v[k].z;
            acc[k].w += wt * v[k].w;
        }
    }

    // ---- block combine ----
    #pragma unroll
    for (int k = 0; k < 8; ++k)
        *reinterpret_cast<float4*>(&s_acc[wid * HE_ + lane * 4 + k * 128]) = acc[k];
    if (lane == 0) { s_m[wid] = m; s_z[wid] = z; }
    __syncthreads();

    const float M = fmaxf(fmaxf(s_m[0], s_m[1]), fmaxf(s_m[2], s_m[3]));
    float ew[NW];
    float Z = 0.f;
    #pragma unroll
    for (int w = 0; w < NW; ++w) {
        ew[w] = __expf(s_m[w] - M);
        Z += ew[w] * s_z[w];
    }

    // each thread combines 8 channels, write split partial
    {
        float4 o0 = make_float4(0.f, 0.f, 0.f, 0.f);
        float4 o1 = make_float4(0.f, 0.f, 0.f, 0.f);
        #pragma unroll
        for (int w = 0; w < NW; ++w) {
            const float4 a0 = *reinterpret_cast<const float4*>(&s_acc[w * HE_ + tid * 8]);
            const float4 a1 = *reinterpret_cast<const float4*>(&s_acc[w * HE_ + tid * 8 + 4]);
            o0.x += ew[w] * a0.x; o0.y += ew[w] * a0.y; o0.z += ew[w] * a0.z; o0.w += ew[w] * a0.w;
            o1.x += ew[w] * a1.x; o1.y += ew[w] * a1.y; o1.z += ew[w] * a1.z; o1.w += ew[w] * a1.w;
        }
        const int ps_idx = b * S_ + s;
        *reinterpret_cast<float4*>(g_acc + (size_t)ps_idx * HE_ + tid * 8)     = o0;
        *reinterpret_cast<float4*>(g_acc + (size_t)ps_idx * HE_ + tid * 8 + 4) = o1;
        if (tid == 0) { g_m[ps_idx] = M; g_z[ps_idx] = Z; }
    }

    // ---- last CTA of this batch merges all splits ----
    __threadfence();
    __syncthreads();
    if (tid == 0) {
        const int prev = atomicAdd(&g_cnt[b], 1);
        s_last = (prev == S_ - 1);
    }
    __syncthreads();
    if (!s_last) return;
    __threadfence();

    // pass A: global max over splits
    float Mf = -CUDART_INF_F;
    #pragma unroll 8
    for (int q = 0; q < S_; ++q) Mf = fmaxf(Mf, g_m[b * S_ + q]);
    // pass B: normalizer
    float Zf = 0.f;
    #pragma unroll 8
    for (int q = 0; q < S_; ++q)
        Zf += __expf(g_m[b * S_ + q] - Mf) * g_z[b * S_ + q];
    const float inv = 1.f / Zf;

    // pass C: accumulate splits (128 threads × 8 channels)
    float4 o0 = make_float4(0.f, 0.f, 0.f, 0.f);
    float4 o1 = make_float4(0.f, 0.f, 0.f, 0.f);
    #pragma unroll 8
    for (int q = 0; q < S_; ++q) {
        const float eq = __expf(g_m[b * S_ + q] - Mf);
        const float4 a0 = *reinterpret_cast<const float4*>(
            g_acc + (size_t)(b * S_ + q) * HE_ + tid * 8);
        const float4 a1 = *reinterpret_cast<const float4*>(
            g_acc + (size_t)(b * S_ + q) * HE_ + tid * 8 + 4);
        o0.x += eq * a0.x; o0.y += eq * a0.y; o0.z += eq * a0.z; o0.w += eq * a0.w;
        o1.x += eq * a1.x; o1.y += eq * a1.y; o1.z += eq * a1.z; o1.w += eq * a1.w;
    }
    o0.x *= inv; o0.y *= inv; o0.z *= inv; o0.w *= inv;
    o1.x *= inv; o1.y *= inv; o1.z *= inv; o1.w *= inv;
    *reinterpret_cast<float4*>(out + (size_t)b * HE_ + tid * 8)     = o0;
    *reinterpret_cast<float4*>(out + (size_t)b * HE_ + tid * 8 + 4) = o1;

    if (tid == 0) g_cnt[b] = 0;   // reset for next graph replay
}

extern "C" void kernel_launch(void* const* d_in, const int* in_sizes, int n_in,
                              void* d_out, int out_size)
{
    const float* hidden = (const float*)d_in[0];
    const float* enc    = (const float*)d_in[1];
    const float* mask   = (const float*)d_in[2];
    const float* attn_w = (const float*)d_in[3];
    const float* attn_b = (const float*)d_in[4];
    float* out = (float*)d_out;

    attn_fused<<<dim3(B_, S_), NT>>>(hidden, enc, mask, attn_w, attn_b, out);
}

// round 7
// speedup vs baseline: 1.0005x; 1.0005x over previous
#include <cuda_runtime.h>
#include <math_constants.h>

#define B_    32
#define T_    2048
#define HE_   1024
#define DECF  2048
#define S_    16
#define CHUNK (T_ / S_)          // 128 rows per CTA
#define NW    4                  // warps per CTA
#define NT    (NW * 32)          // 128 threads
#define RPW   (CHUNK / NW)       // 32 rows per warp

// Split partials + completion counters (allocation-free scratch, zero-init)
__device__ float g_m  [B_ * S_];
__device__ float g_z  [B_ * S_];
__device__ __align__(16) float g_acc[B_ * S_ * HE_];
__device__ int   g_cnt[B_];

__device__ __forceinline__ void load_row(float4 (&v)[8], const float* __restrict__ p)
{
    #pragma unroll
    for (int k = 0; k < 8; ++k)
        v[k] = *reinterpret_cast<const float4*>(p + k * 128);
}

__device__ __forceinline__ void process_row(const float4 (&v)[8],
                                            const float* __restrict__ s_we,
                                            const int lane,
                                            const float mk, const float hid_dot,
                                            float& m, float& z, float4 (&acc)[8])
{
    float d = 0.f;
    #pragma unroll
    for (int k = 0; k < 8; ++k) {
        const float4 w4 = *reinterpret_cast<const float4*>(&s_we[lane * 4 + k * 128]);
        d += v[k].x * w4.x + v[k].y * w4.y + v[k].z * w4.z + v[k].w * w4.w;
    }
    #pragma unroll
    for (int o = 16; o > 0; o >>= 1) d += __shfl_xor_sync(0xffffffffu, d, o);

    const float e = (d + hid_dot) * mk;
    const float mnew = fmaxf(m, e);
    if (mnew > m) {                      // warp-uniform branch
        const float sc = __expf(m - mnew);
        z *= sc;
        #pragma unroll
        for (int k = 0; k < 8; ++k) {
            acc[k].x *= sc; acc[k].y *= sc; acc[k].z *= sc; acc[k].w *= sc;
        }
        m = mnew;
    }
    const float wt = mk * __expf(e - m);
    z += wt;
    #pragma unroll
    for (int k = 0; k < 8; ++k) {
        acc[k].x += wt * v[k].x;
        acc[k].y += wt * v[k].y;
        acc[k].z += wt * v[k].z;
        acc[k].w += wt * v[k].w;
    }
}

__global__ __launch_bounds__(NT, 4)
void attn_fused(const float* __restrict__ hidden,   // (2,32,1024)
                const float* __restrict__ enc,      // (32,2048,1024)
                const float* __restrict__ mask,     // (32,2048)
                const float* __restrict__ attn_w,   // (3072,)
                const float* __restrict__ attn_b,   // (1,)
                float* __restrict__ out)            // (32,1024)
{
    const int b    = blockIdx.x;
    const int s    = blockIdx.y;
    const int tid  = threadIdx.x;
    const int wid  = tid >> 5;
    const int lane = tid & 31;

    __shared__ float s_red[NW];
    __shared__ float s_hid;
    __shared__ float s_m[NW], s_z[NW];
    __shared__ __align__(16) float s_we[HE_];         // 4 KB
    __shared__ __align__(16) float s_acc[NW * HE_];   // 16 KB
    __shared__ int s_last;

    // ---- stage w_e into shared ----
    #pragma unroll
    for (int k = 0; k < HE_ / NT; ++k)
        s_we[tid + k * NT] = attn_w[DECF + tid + k * NT];

    // ---- hid_dot[b] = hid_flat[b,:] @ w_h + attn_b ----
    {
        float ps = 0.f;
        #pragma unroll
        for (int k = 0; k < DECF / NT; ++k) {
            const int f = tid + k * NT;               // 0..2047
            ps += hidden[(size_t)(f >> 10) * (B_ * HE_) + (size_t)b * HE_ + (f & 1023)]
                  * attn_w[f];
        }
        #pragma unroll
        for (int o = 16; o > 0; o >>= 1) ps += __shfl_xor_sync(0xffffffffu, ps, o);
        if (lane == 0) s_red[wid] = ps;
        __syncthreads();
        if (tid == 0) {
            float h = attn_b[0];
            #pragma unroll
            for (int w = 0; w < NW; ++w) h += s_red[w];
            s_hid = h;
        }
        __syncthreads();
    }
    const float hid_dot = s_hid;

    // ---- warp-private online softmax, double-buffered rows ----
    float m = -CUDART_INF_F;
    float z = 0.f;
    float4 acc[8];
    #pragma unroll
    for (int k = 0; k < 8; ++k) acc[k] = make_float4(0.f, 0.f, 0.f, 0.f);

    const int r0 = s * CHUNK + wid * RPW;
    const float* encB = enc  + (size_t)b * T_ * HE_;
    const float* mskB = mask + (size_t)b * T_;

    const float* rowp = encB + (size_t)r0 * HE_ + lane * 4;
    float4 va[8], vb[8];
    load_row(va, rowp);

    #pragma unroll 1
    for (int i = 0; i < RPW; i += 2) {
        // prefetch row i+1 while row i's chain runs
        load_row(vb, rowp + HE_);
        const float mk0 = __ldg(mskB + r0 + i);
        const float mk1 = __ldg(mskB + r0 + i + 1);
        process_row(va, s_we, lane, mk0, hid_dot, m, z, acc);

        // prefetch row i+2 while row i+1's chain runs
        if (i + 2 < RPW) load_row(va, rowp + 2 * HE_);
        process_row(vb, s_we, lane, mk1, hid_dot, m, z, acc);

        rowp += 2 * HE_;
    }

    // ---- block combine ----
    #pragma unroll
    for (int k = 0; k < 8; ++k)
        *reinterpret_cast<float4*>(&s_acc[wid * HE_ + lane * 4 + k * 128]) = acc[k];
    if (lane == 0) { s_m[wid] = m; s_z[wid] = z; }
    __syncthreads();

    const float M = fmaxf(fmaxf(s_m[0], s_m[1]), fmaxf(s_m[2], s_m[3]));
    float ew[NW];
    float Z = 0.f;
    #pragma unroll
    for (int w = 0; w < NW; ++w) {
        ew[w] = __expf(s_m[w] - M);
        Z += ew[w] * s_z[w];
    }

    // each thread combines 8 channels, write split partial
    {
        float4 o0 = make_float4(0.f, 0.f, 0.f, 0.f);
        float4 o1 = make_float4(0.f, 0.f, 0.f, 0.f);
        #pragma unroll
        for (int w = 0; w < NW; ++w) {
            const float4 a0 = *reinterpret_cast<const float4*>(&s_acc[w * HE_ + tid * 8]);
            const float4 a1 = *reinterpret_cast<const float4*>(&s_acc[w * HE_ + tid * 8 + 4]);
            o0.x += ew[w] * a0.x; o0.y += ew[w] * a0.y; o0.z += ew[w] * a0.z; o0.w += ew[w] * a0.w;
            o1.x += ew[w] * a1.x; o1.y += ew[w] * a1.y; o1.z += ew[w] * a1.z; o1.w += ew[w] * a1.w;
        }
        const int ps_idx = b * S_ + s;
        *reinterpret_cast<float4*>(g_acc + (size_t)ps_idx * HE_ + tid * 8)     = o0;
        *reinterpret_cast<float4*>(g_acc + (size_t)ps_idx * HE_ + tid * 8 + 4) = o1;
        if (tid == 0) { g_m[ps_idx] = M; g_z[ps_idx] = Z; }
    }

    // ---- last CTA of this batch merges all splits ----
    __threadfence();
    __syncthreads();
    if (tid == 0) {
        const int prev = atomicAdd(&g_cnt[b], 1);
        s_last = (prev == S_ - 1);
    }
    __syncthreads();
    if (!s_last) return;
    __threadfence();

    float Mf = -CUDART_INF_F;
    #pragma unroll
    for (int q = 0; q < S_; ++q) Mf = fmaxf(Mf, g_m[b * S_ + q]);
    float Zf = 0.f;
    #pragma unroll
    for (int q = 0; q < S_; ++q)
        Zf += __expf(g_m[b * S_ + q] - Mf) * g_z[b * S_ + q];
    const float inv = 1.f / Zf;

    float4 o0 = make_float4(0.f, 0.f, 0.f, 0.f);
    float4 o1 = make_float4(0.f, 0.f, 0.f, 0.f);
    #pragma unroll
    for (int q = 0; q < S_; ++q) {
        const float eq = __expf(g_m[b * S_ + q] - Mf);
        const float4 a0 = *reinterpret_cast<const float4*>(
            g_acc + (size_t)(b * S_ + q) * HE_ + tid * 8);
        const float4 a1 = *reinterpret_cast<const float4*>(
            g_acc + (size_t)(b * S_ + q) * HE_ + tid * 8 + 4);
        o0.x += eq * a0.x; o0.y += eq * a0.y; o0.z += eq * a0.z; o0.w += eq * a0.w;
        o1.x += eq * a1.x; o1.y += eq * a1.y; o1.z += eq * a1.z; o1.w += eq * a1.w;
    }
    o0.x *= inv; o0.y *= inv; o0.z *= inv; o0.w *= inv;
    o1.x *= inv; o1.y *= inv; o1.z *= inv; o1.w *= inv;
    *reinterpret_cast<float4*>(out + (size_t)b * HE_ + tid * 8)     = o0;
    *reinterpret_cast<float4*>(out + (size_t)b * HE_ + tid * 8 + 4) = o1;

    if (tid == 0) g_cnt[b] = 0;   // reset for next graph replay
}

extern "C" void kernel_launch(void* const* d_in, const int* in_sizes, int n_in,
                              void* d_out, int out_size)
{
    const float* hidden = (const float*)d_in[0];
    const float* enc    = (const float*)d_in[1];
    const float* mask   = (const float*)d_in[2];
    const float* attn_w = (const float*)d_in[3];
    const float* attn_b = (const float*)d_in[4];
    float* out = (float*)d_out;

    attn_fused<<<dim3(B_, S_), NT>>>(hidden, enc, mask, attn_w, attn_b, out);
}

// round 8
// speedup vs baseline: 1.1954x; 1.1948x over previous
#include <cuda_runtime.h>
#include <math_constants.h>

#define B_    32
#define T_    2048
#define HE_   1024
#define DECF  2048
#define S_    16
#define CHUNK (T_ / S_)          // 128 rows per CTA
#define NW    4                  // warps per CTA
#define NT    (NW * 32)          // 128 threads
#define RPW   (CHUNK / NW)       // 32 rows per warp

// Split partials + completion counters (allocation-free scratch, zero-init)
__device__ float g_m  [B_ * S_];
__device__ float g_z  [B_ * S_];
__device__ __align__(16) float g_acc[B_ * S_ * HE_];
__device__ int   g_cnt[B_];

__global__ __launch_bounds__(NT, 4)
void attn_fused(const float* __restrict__ enc,      // (32,2048,1024)
                const float* __restrict__ mask,     // (32,2048)
                const float* __restrict__ attn_w,   // (3072,)
                float* __restrict__ out)            // (32,1024)
{
    const int b    = blockIdx.x;
    const int s    = blockIdx.y;
    const int tid  = threadIdx.x;
    const int wid  = tid >> 5;
    const int lane = tid & 31;

    __shared__ float s_m[NW], s_z[NW];
    __shared__ __align__(16) float s_acc[NW * HE_];   // 16 KB
    __shared__ int s_last;

    // w_e slice in registers (hid_dot cancels in the normalized softmax -> dropped)
    float4 we[8];
    #pragma unroll
    for (int k = 0; k < 8; ++k)
        we[k] = *reinterpret_cast<const float4*>(attn_w + DECF + lane * 4 + k * 128);

    // ---- warp-private online softmax over RPW rows (no barriers, no startup) ----
    float m = -CUDART_INF_F;
    float z = 0.f;
    float4 acc[8];
    #pragma unroll
    for (int k = 0; k < 8; ++k) acc[k] = make_float4(0.f, 0.f, 0.f, 0.f);

    const int r0 = s * CHUNK + wid * RPW;
    const float* encB = enc  + (size_t)b * T_ * HE_;
    const float* mskB = mask + (size_t)b * T_;

    for (int i = 0; i < RPW; ++i) {
        const int r = r0 + i;
        const float* row = encB + (size_t)r * HE_ + lane * 4;

        float4 v[8];
        #pragma unroll
        for (int k = 0; k < 8; ++k)
            v[k] = __ldcs(reinterpret_cast<const float4*>(row + k * 128));

        float d = 0.f;
        #pragma unroll
        for (int k = 0; k < 8; ++k)
            d += v[k].x * we[k].x + v[k].y * we[k].y + v[k].z * we[k].z + v[k].w * we[k].w;
        #pragma unroll
        for (int o = 16; o > 0; o >>= 1) d += __shfl_xor_sync(0xffffffffu, d, o);

        const float mk = __ldg(mskB + r);
        const float e  = d * mk;          // hid_dot omitted (cancels after renorm)

        const float mnew = fmaxf(m, e);
        if (mnew > m) {                   // warp-uniform branch
            const float sc = __expf(m - mnew);
            z *= sc;
            #pragma unroll
            for (int k = 0; k < 8; ++k) {
                acc[k].x *= sc; acc[k].y *= sc; acc[k].z *= sc; acc[k].w *= sc;
            }
            m = mnew;
        }
        const float wt = mk * __expf(e - m);
        z += wt;
        #pragma unroll
        for (int k = 0; k < 8; ++k) {
            acc[k].x += wt * v[k].x;
            acc[k].y += wt * v[k].y;
            acc[k].z += wt * v[k].z;
            acc[k].w += wt * v[k].w;
        }
    }

    // ---- block combine (first barrier of the kernel) ----
    #pragma unroll
    for (int k = 0; k < 8; ++k)
        *reinterpret_cast<float4*>(&s_acc[wid * HE_ + lane * 4 + k * 128]) = acc[k];
    if (lane == 0) { s_m[wid] = m; s_z[wid] = z; }
    __syncthreads();

    const float M = fmaxf(fmaxf(s_m[0], s_m[1]), fmaxf(s_m[2], s_m[3]));
    float ew[NW];
    float Z = 0.f;
    #pragma unroll
    for (int w = 0; w < NW; ++w) {
        ew[w] = __expf(s_m[w] - M);
        Z += ew[w] * s_z[w];
    }

    // each thread combines 8 channels, write split partial
    {
        float4 o0 = make_float4(0.f, 0.f, 0.f, 0.f);
        float4 o1 = make_float4(0.f, 0.f, 0.f, 0.f);
        #pragma unroll
        for (int w = 0; w < NW; ++w) {
            const float4 a0 = *reinterpret_cast<const float4*>(&s_acc[w * HE_ + tid * 8]);
            const float4 a1 = *reinterpret_cast<const float4*>(&s_acc[w * HE_ + tid * 8 + 4]);
            o0.x += ew[w] * a0.x; o0.y += ew[w] * a0.y; o0.z += ew[w] * a0.z; o0.w += ew[w] * a0.w;
            o1.x += ew[w] * a1.x; o1.y += ew[w] * a1.y; o1.z += ew[w] * a1.z; o1.w += ew[w] * a1.w;
        }
        const int ps_idx = b * S_ + s;
        *reinterpret_cast<float4*>(g_acc + (size_t)ps_idx * HE_ + tid * 8)     = o0;
        *reinterpret_cast<float4*>(g_acc + (size_t)ps_idx * HE_ + tid * 8 + 4) = o1;
        if (tid == 0) { g_m[ps_idx] = M; g_z[ps_idx] = Z; }
    }

    // ---- last CTA of this batch merges all splits ----
    __threadfence();
    __syncthreads();
    if (tid == 0) {
        const int prev = atomicAdd(&g_cnt[b], 1);
        s_last = (prev == S_ - 1);
    }
    __syncthreads();
    if (!s_last) return;
    __threadfence();

    float Mf = -CUDART_INF_F;
    #pragma unroll
    for (int q = 0; q < S_; ++q) Mf = fmaxf(Mf, g_m[b * S_ + q]);
    float Zf = 0.f;
    #pragma unroll
    for (int q = 0; q < S_; ++q)
        Zf += __expf(g_m[b * S_ + q] - Mf) * g_z[b * S_ + q];
    const float inv = 1.f / Zf;

    float4 o0 = make_float4(0.f, 0.f, 0.f, 0.f);
    float4 o1 = make_float4(0.f, 0.f, 0.f, 0.f);
    #pragma unroll
    for (int q = 0; q < S_; ++q) {
        const float eq = __expf(g_m[b * S_ + q] - Mf);
        const float4 a0 = *reinterpret_cast<const float4*>(
            g_acc + (size_t)(b * S_ + q) * HE_ + tid * 8);
        const float4 a1 = *reinterpret_cast<const float4*>(
            g_acc + (size_t)(b * S_ + q) * HE_ + tid * 8 + 4);
        o0.x += eq * a0.x; o0.y += eq * a0.y; o0.z += eq * a0.z; o0.w += eq * a0.w;
        o1.x += eq * a1.x; o1.y += eq * a1.y; o1.z += eq * a1.z; o1.w += eq * a1.w;
    }
    o0.x *= inv; o0.y *= inv; o0.z *= inv; o0.w *= inv;
    o1.x *= inv; o1.y *= inv; o1.z *= inv; o1.w *= inv;
    *reinterpret_cast<float4*>(out + (size_t)b * HE_ + tid * 8)     = o0;
    *reinterpret_cast<float4*>(out + (size_t)b * HE_ + tid * 8 + 4) = o1;

    if (tid == 0) g_cnt[b] = 0;   // reset for next graph replay
}

extern "C" void kernel_launch(void* const* d_in, const int* in_sizes, int n_in,
                              void* d_out, int out_size)
{
    const float* enc    = (const float*)d_in[1];
    const float* mask   = (const float*)d_in[2];
    const float* attn_w = (const float*)d_in[3];
    float* out = (float*)d_out;

    attn_fused<<<dim3(B_, S_), NT>>>(enc, mask, attn_w, out);
}